// round 16
// baseline (speedup 1.0000x reference)
#include <cuda_runtime.h>
#include <cuda_bf16.h>
#include <cuda_fp16.h>
#include <cstdint>

#define DD 128
#define MAXN 50016
#define MAXE 800000
#define PADE (MAXE + 4 * MAXN)   // padded CSR capacity
#define NB_SCAN 148              // scan/fill blocks (co-resident => grid barrier ok)

// ---------------- scratch (device globals; allocation-free) ----------------
__device__ __align__(16) __half g_y16[(size_t)MAXN * DD];     // post-agg (fp16)
__device__ __align__(16) __half g_x16[(size_t)MAXN * DD];     // fp16 input copy
__device__ __align__(16) __half g_act16[(size_t)MAXN * DD];   // fp16 activations
__device__ __align__(16) __half g_w16[3 * DD * DD];           // W^T fp16 per layer
__device__ float g_dinv[MAXN];
__device__ __align__(16) int g_cnt[MAXN];   // static-zero; re-zeroed by scanfill each call
__device__ int   g_off[MAXN + 1];
__device__ int   g_cur[MAXN];
__device__ __align__(16) int   g_esrc[PADE];
__device__ __align__(16) float g_ew[PADE];
__device__ int   g_partial[256];
__device__ int   g_flag1;
__device__ int   g_flag2;

// ---------------------------------------------------------------------------
// prep: count atomics + W transpose->fp16 + x->fp16 + flag resets. One launch.
// ---------------------------------------------------------------------------
__global__ __launch_bounds__(256) void prep_kernel(
    const int* __restrict__ dst, int* __restrict__ cnt, int E, int ncb,
    const float* __restrict__ W1, const float* __restrict__ W2,
    const float* __restrict__ W3, __half* __restrict__ w16, int wsb,
    const float* __restrict__ x, __half* __restrict__ x16, int tot4,
    int* __restrict__ flag1, int* __restrict__ flag2) {
    int b = (int)blockIdx.x;
    int t = threadIdx.x;
    if (b == 0 && t == 0) {
        *flag1 = 0;
        *flag2 = 0;
    }
    if (b < ncb) {
        int e = b * 256 + t;
        if (e < E) atomicAdd(&cnt[dst[e]], 1);
    } else if (b < ncb + wsb) {
        int i = (b - ncb) * 256 + t;
        if (i < 3 * DD * DD) {
            int layer = i / (DD * DD);
            int j = i - layer * (DD * DD);
            const float* W = (layer == 0) ? W1 : ((layer == 1) ? W2 : W3);
            int nn = j >> 7, kk = j & 127;
            w16[i] = __float2half(W[kk * DD + nn]);
        }
    } else {
        int i = (b - ncb - wsb) * 256 + t;
        if (i < tot4) {
            float4 v = ((const float4*)x)[i];
            __half2 a = __floats2half2_rn(v.x, v.y);
            __half2 c = __floats2half2_rn(v.z, v.w);
            uint2 u;
            u.x = *(uint32_t*)&a;
            u.y = *(uint32_t*)&c;
            ((uint2*)x16)[i] = u;
        }
    }
}

// ---------------------------------------------------------------------------
// scanfill: NB_SCAN x 1024, grid barriers. CSR segments padded to multiple of
// 4 (padding slots zero-weight) so agg can use int4/float4 edge-meta loads.
// ---------------------------------------------------------------------------
__global__ __launch_bounds__(1024) void scanfill_kernel(
    int* __restrict__ cnt, int* __restrict__ off, int* __restrict__ cur,
    float* __restrict__ dinv, const int* __restrict__ src,
    const int* __restrict__ dst, int* __restrict__ esrc, float* __restrict__ ew,
    int* __restrict__ partial, int* __restrict__ flag1, int* __restrict__ flag2,
    int n, int E, int ch) {
    __shared__ int wsum[32];
    __shared__ int sp[NB_SCAN];
    __shared__ int s_base;

    const int b = (int)blockIdx.x;
    const int t = threadIdx.x;
    const int lane = t & 31;
    const int w = t >> 5;
    const int nb = (int)gridDim.x;

    // ---- phase 1: local chunk scan over PADDED counts ----
    int i = b * ch + t;
    int c = (t < ch && i < n) ? cnt[i] : 0;
    int pc = (c + 3) & ~3;  // pad to multiple of 4
    int incl = pc;
#pragma unroll
    for (int o = 1; o < 32; o <<= 1) {
        int u = __shfl_up_sync(0xffffffffu, incl, o);
        if (lane >= o) incl += u;
    }
    if (lane == 31) wsum[w] = incl;
    __syncthreads();
    if (t < 32) {
        int v = wsum[t];
        int orig = v;
#pragma unroll
        for (int o = 1; o < 32; o <<= 1) {
            int u = __shfl_up_sync(0xffffffffu, v, o);
            if (t >= o) v += u;
        }
        int total = __shfl_sync(0xffffffffu, v, 31);
        wsum[t] = v - orig;
        if (t == 0) {
            partial[b] = total;
            __threadfence();
            atomicAdd(flag1, 1);
            while (atomicAdd(flag1, 0) < nb) {}
            __threadfence();
        }
    }
    __syncthreads();

    // ---- phase 2: top scan of nb partials ----
    if (t < nb) sp[t] = partial[t];
    __syncthreads();
    for (int o = 1; o < nb; o <<= 1) {
        int v = (t < nb && t >= o) ? sp[t - o] : 0;
        __syncthreads();
        if (t < nb) sp[t] += v;
        __syncthreads();
    }
    if (t == 0) s_base = (b == 0) ? 0 : sp[b - 1];
    __syncthreads();

    int run = s_base + wsum[w] + (incl - pc);
    if (t < ch && i < n) {
        off[i] = run;
        cur[i] = run;
        dinv[i] = rsqrtf((float)(c + 1));
        cnt[i] = 0;
        // zero the padding slots [run+c, run+pc)
        for (int p = run + c; p < run + pc; ++p) {
            esrc[p] = 0;
            ew[p] = 0.f;
        }
    }
    if (b == 0 && t == 0) off[n] = sp[nb - 1];

    // ---- grid barrier 2 ----
    __threadfence();
    __syncthreads();
    if (t == 0) {
        atomicAdd(flag2, 1);
        while (atomicAdd(flag2, 0) < nb) {}
        __threadfence();
    }
    __syncthreads();

    // ---- phase 3: CSR fill (grid-stride) ----
    for (int e = b * 1024 + t; e < E; e += nb * 1024) {
        int s = src[e];
        int d = dst[e];
        int pos = atomicAdd(&cur[d], 1);
        esrc[pos] = s;
        ew[pos] = dinv[s] * dinv[d];
    }
}

// ---------------------------------------------------------------------------
// Aggregation: fp16 gather, fp32 accumulate, fp16 out. Padded-4 CSR:
// per 4 edges one int4 + one float4 meta load, no tail loop.
// ---------------------------------------------------------------------------
__device__ __forceinline__ void fma_h4(float4& acc, float w, uint2 u) {
    __half2 a = *(__half2*)&u.x;
    __half2 b = *(__half2*)&u.y;
    float2 fa = __half22float2(a);
    float2 fb = __half22float2(b);
    acc.x = fmaf(w, fa.x, acc.x);
    acc.y = fmaf(w, fa.y, acc.y);
    acc.z = fmaf(w, fb.x, acc.z);
    acc.w = fmaf(w, fb.y, acc.w);
}

__global__ __launch_bounds__(256) void agg_kernel(const __half* __restrict__ h16,
                                                  const float* __restrict__ dinv,
                                                  const int* __restrict__ off,
                                                  const int* __restrict__ esrc,
                                                  const float* __restrict__ ew,
                                                  __half* __restrict__ out16, int n) {
    int node = (blockIdx.x * blockDim.x + threadIdx.x) >> 5;
    int lane = threadIdx.x & 31;
    if (node >= n) return;

    const uint2* __restrict__ h2 = (const uint2*)h16;
    float di = dinv[node];
    float wself = di * di;
    float4 acc = make_float4(0.f, 0.f, 0.f, 0.f);
    fma_h4(acc, wself, h2[(size_t)node * 32 + lane]);

    int e = off[node], e1 = off[node + 1];
    for (; e < e1; e += 4) {
        int4 si = __ldg((const int4*)(esrc + e));
        float4 wf = __ldg((const float4*)(ew + e));
        uint2 v0 = h2[(size_t)si.x * 32 + lane];
        uint2 v1 = h2[(size_t)si.y * 32 + lane];
        uint2 v2 = h2[(size_t)si.z * 32 + lane];
        uint2 v3 = h2[(size_t)si.w * 32 + lane];
        fma_h4(acc, wf.x, v0);
        fma_h4(acc, wf.y, v1);
        fma_h4(acc, wf.z, v2);
        fma_h4(acc, wf.w, v3);
    }
    __half2 o0 = __floats2half2_rn(acc.x, acc.y);
    __half2 o1 = __floats2half2_rn(acc.z, acc.w);
    uint2 u;
    u.x = *(uint32_t*)&o0;
    u.y = *(uint32_t*)&o1;
    ((uint2*)out16)[(size_t)node * 32 + lane] = u;
}

// ---------------------------------------------------------------------------
// fp16 HMMA GEMM, re-tiled for occupancy: CTA = 128 rows x 64 cols (gy picks
// column half). 8 warps x (16 rows x 64 cols) => 32 accs/thread, ~17.4KB smem.
// ---------------------------------------------------------------------------
#define BSTRIDE_U32 68

__device__ __forceinline__ void mma_f16(float* c, const uint32_t* a, uint32_t b0, uint32_t b1) {
    asm volatile(
        "mma.sync.aligned.m16n8k16.row.col.f32.f16.f16.f32 "
        "{%0,%1,%2,%3}, {%4,%5,%6,%7}, {%8,%9}, {%0,%1,%2,%3};"
        : "+f"(c[0]), "+f"(c[1]), "+f"(c[2]), "+f"(c[3])
        : "r"(a[0]), "r"(a[1]), "r"(a[2]), "r"(a[3]), "r"(b0), "r"(b1));
}

template <int RELU, int F16OUT>
__global__ __launch_bounds__(256, 3) void gemm_f16_kernel(
    const __half* __restrict__ A,
    const __half* __restrict__ Wt,
    const float* __restrict__ bias, float* __restrict__ C32,
    __half* __restrict__ C16, int n) {
    extern __shared__ uint32_t sB[];  // 64 * 68 u32 = 17,408 B

    const int tid = threadIdx.x;
    const int warp = tid >> 5;
    const int lane = tid & 31;
    const int quad = lane >> 2;
    const int tq = lane & 3;
    const int row0 = blockIdx.x * 128;
    const int col0 = blockIdx.y * 64;

    // stage 64 Wt rows (output cols col0..col0+63), 64 u32 each
    const uint32_t* W32 = (const uint32_t*)Wt;
#pragma unroll
    for (int i = tid; i < 64 * 64; i += 256) {
        int r = i >> 6, kp = i & 63;
        sB[r * BSTRIDE_U32 + kp] = W32[(size_t)(col0 + r) * 64 + kp];
    }
    __syncthreads();

    const int row_lo = row0 + warp * 16 + quad;
    const int row_hi = row_lo + 8;
    const bool ok_lo = row_lo < n;
    const bool ok_hi = row_hi < n;

    float acc[8][4];
#pragma unroll
    for (int t = 0; t < 8; ++t)
#pragma unroll
        for (int j = 0; j < 4; ++j) acc[t][j] = 0.f;

#pragma unroll
    for (int ks = 0; ks < 8; ++ks) {
        const int k0 = ks * 16;
        uint32_t a[4];
        {
            size_t base_lo = (size_t)row_lo * DD + k0 + 2 * tq;
            size_t base_hi = (size_t)row_hi * DD + k0 + 2 * tq;
            a[0] = ok_lo ? *(const uint32_t*)(A + base_lo) : 0u;
            a[1] = ok_hi ? *(const uint32_t*)(A + base_hi) : 0u;
            a[2] = ok_lo ? *(const uint32_t*)(A + base_lo + 8) : 0u;
            a[3] = ok_hi ? *(const uint32_t*)(A + base_hi + 8) : 0u;
        }
        const int kbase = (k0 >> 1) + tq;
#pragma unroll
        for (int nt = 0; nt < 8; ++nt) {
            int brow = nt * 8 + quad;
            uint32_t b0 = sB[brow * BSTRIDE_U32 + kbase];
            uint32_t b1 = sB[brow * BSTRIDE_U32 + kbase + 4];
            mma_f16(acc[nt], a, b0, b1);
        }
    }

#pragma unroll
    for (int nt = 0; nt < 8; ++nt) {
        int col = col0 + nt * 8 + 2 * tq;
        float2 bv = *(const float2*)(bias + col);
        float c0 = acc[nt][0] + bv.x, c1 = acc[nt][1] + bv.y;
        float c2 = acc[nt][2] + bv.x, c3 = acc[nt][3] + bv.y;
        if (RELU) {
            c0 = fmaxf(c0, 0.f); c1 = fmaxf(c1, 0.f);
            c2 = fmaxf(c2, 0.f); c3 = fmaxf(c3, 0.f);
        }
        if (F16OUT) {
            if (ok_lo) *(__half2*)(C16 + (size_t)row_lo * DD + col) = __floats2half2_rn(c0, c1);
            if (ok_hi) *(__half2*)(C16 + (size_t)row_hi * DD + col) = __floats2half2_rn(c2, c3);
        } else {
            if (ok_lo) *(float2*)(C32 + (size_t)row_lo * DD + col) = make_float2(c0, c1);
            if (ok_hi) *(float2*)(C32 + (size_t)row_hi * DD + col) = make_float2(c2, c3);
        }
    }
}

// ---------------------------------------------------------------------------
// Launch: 8 kernels total (prep, scanfill, 3x[agg, gemm])
// ---------------------------------------------------------------------------
extern "C" void kernel_launch(void* const* d_in, const int* in_sizes, int n_in,
                              void* d_out, int out_size) {
    const float* x  = (const float*)d_in[0];
    const int*   ei = (const int*)d_in[1];
    const float* W1 = (const float*)d_in[2];
    const float* b1 = (const float*)d_in[3];
    const float* W2 = (const float*)d_in[4];
    const float* b2 = (const float*)d_in[5];
    const float* W3 = (const float*)d_in[6];
    const float* b3 = (const float*)d_in[7];

    int n = in_sizes[0] / DD;
    int E = in_sizes[1] / 2;
    const int* src = ei;
    const int* dst = ei + E;

    float *dinv, *ew;
    __half *y16, *x16, *act16, *w16;
    int *cnt, *off, *cur, *esrc, *partial, *flag1, *flag2;
    cudaGetSymbolAddress((void**)&y16, g_y16);
    cudaGetSymbolAddress((void**)&x16, g_x16);
    cudaGetSymbolAddress((void**)&act16, g_act16);
    cudaGetSymbolAddress((void**)&w16, g_w16);
    cudaGetSymbolAddress((void**)&dinv, g_dinv);
    cudaGetSymbolAddress((void**)&cnt, g_cnt);
    cudaGetSymbolAddress((void**)&off, g_off);
    cudaGetSymbolAddress((void**)&cur, g_cur);
    cudaGetSymbolAddress((void**)&esrc, g_esrc);
    cudaGetSymbolAddress((void**)&ew, g_ew);
    cudaGetSymbolAddress((void**)&partial, g_partial);
    cudaGetSymbolAddress((void**)&flag1, g_flag1);
    cudaGetSymbolAddress((void**)&flag2, g_flag2);

    float* outp = (float*)d_out;

    const int GEMM_SMEM = 64 * BSTRIDE_U32 * 4;  // 17,408 B
    cudaFuncSetAttribute(gemm_f16_kernel<1, 1>, cudaFuncAttributeMaxDynamicSharedMemorySize,
                         GEMM_SMEM);
    cudaFuncSetAttribute(gemm_f16_kernel<0, 0>, cudaFuncAttributeMaxDynamicSharedMemorySize,
                         GEMM_SMEM);

    int tot4 = n * (DD / 4);
    int ncb = (E + 255) / 256;
    int wsb = (3 * DD * DD + 255) / 256;
    int cvb = (tot4 + 255) / 256;
    int ch = (n + NB_SCAN - 1) / NB_SCAN;

    // --- preprocess: 2 launches ---
    prep_kernel<<<ncb + wsb + cvb, 256>>>(dst, cnt, E, ncb, W1, W2, W3, w16, wsb, x, x16,
                                          tot4, flag1, flag2);
    scanfill_kernel<<<NB_SCAN, 1024>>>(cnt, off, cur, dinv, src, dst, esrc, ew, partial,
                                       flag1, flag2, n, E, ch);

    dim3 gemm_grid((n + 127) / 128, 2);
    int agg_grid = (n + 7) / 8;

    // Layer 1
    agg_kernel<<<agg_grid, 256>>>(x16, dinv, off, esrc, ew, y16, n);
    gemm_f16_kernel<1, 1><<<gemm_grid, 256, GEMM_SMEM>>>(y16, w16, b1, nullptr, act16, n);
    // Layer 2
    agg_kernel<<<agg_grid, 256>>>(act16, dinv, off, esrc, ew, y16, n);
    gemm_f16_kernel<1, 1><<<gemm_grid, 256, GEMM_SMEM>>>(y16, w16 + DD * DD, b2, nullptr,
                                                         act16, n);
    // Layer 3 (no relu) -> fp32 d_out
    agg_kernel<<<agg_grid, 256>>>(act16, dinv, off, esrc, ew, y16, n);
    gemm_f16_kernel<0, 0><<<gemm_grid, 256, GEMM_SMEM>>>(y16, w16 + 2 * DD * DD, b3, outp,
                                                         nullptr, n);
}

// round 17
// speedup vs baseline: 1.1184x; 1.1184x over previous
#include <cuda_runtime.h>
#include <cuda_bf16.h>
#include <cuda_fp16.h>
#include <cstdint>

#define DD 128
#define MAXN 50016
#define MAXE 800000
#define PADE (MAXE + 4 * MAXN)   // padded CSR capacity
#define NB_SCAN 148              // scan/fill blocks (co-resident => grid barrier ok)

// ---------------- scratch (device globals; allocation-free) ----------------
__device__ __align__(16) __half g_y16[(size_t)MAXN * DD];     // post-agg (fp16)
__device__ __align__(16) __half g_x16[(size_t)MAXN * DD];     // fp16 input copy
__device__ __align__(16) __half g_act16[(size_t)MAXN * DD];   // fp16 activations
__device__ __align__(16) __half g_w16[3 * DD * DD];           // W^T fp16 per layer
__device__ float g_dinv[MAXN];
__device__ __align__(16) int g_cnt[MAXN];   // static-zero; re-zeroed by scanfill each call
__device__ int   g_off[MAXN + 1];
__device__ int   g_cur[MAXN];
__device__ __align__(16) int   g_esrc[PADE];
__device__ __align__(16) float g_ew[PADE];
__device__ int   g_partial[256];
__device__ int   g_flag1;
__device__ int   g_flag2;

// ---------------------------------------------------------------------------
// prep: count atomics + W transpose->fp16 + x->fp16 + flag resets. One launch.
// ---------------------------------------------------------------------------
__global__ __launch_bounds__(256) void prep_kernel(
    const int* __restrict__ dst, int* __restrict__ cnt, int E, int ncb,
    const float* __restrict__ W1, const float* __restrict__ W2,
    const float* __restrict__ W3, __half* __restrict__ w16, int wsb,
    const float* __restrict__ x, __half* __restrict__ x16, int tot4,
    int* __restrict__ flag1, int* __restrict__ flag2) {
    int b = (int)blockIdx.x;
    int t = threadIdx.x;
    if (b == 0 && t == 0) {
        *flag1 = 0;
        *flag2 = 0;
    }
    if (b < ncb) {
        int e = b * 256 + t;
        if (e < E) atomicAdd(&cnt[dst[e]], 1);
    } else if (b < ncb + wsb) {
        int i = (b - ncb) * 256 + t;
        if (i < 3 * DD * DD) {
            int layer = i / (DD * DD);
            int j = i - layer * (DD * DD);
            const float* W = (layer == 0) ? W1 : ((layer == 1) ? W2 : W3);
            int nn = j >> 7, kk = j & 127;
            w16[i] = __float2half(W[kk * DD + nn]);
        }
    } else {
        int i = (b - ncb - wsb) * 256 + t;
        if (i < tot4) {
            float4 v = ((const float4*)x)[i];
            __half2 a = __floats2half2_rn(v.x, v.y);
            __half2 c = __floats2half2_rn(v.z, v.w);
            uint2 u;
            u.x = *(uint32_t*)&a;
            u.y = *(uint32_t*)&c;
            ((uint2*)x16)[i] = u;
        }
    }
}

// ---------------------------------------------------------------------------
// scanfill: NB_SCAN x 1024, grid barriers. CSR segments padded to multiple of
// 4 (padding slots zero-weight) so agg can use int4/float4 edge-meta loads.
// ---------------------------------------------------------------------------
__global__ __launch_bounds__(1024) void scanfill_kernel(
    int* __restrict__ cnt, int* __restrict__ off, int* __restrict__ cur,
    float* __restrict__ dinv, const int* __restrict__ src,
    const int* __restrict__ dst, int* __restrict__ esrc, float* __restrict__ ew,
    int* __restrict__ partial, int* __restrict__ flag1, int* __restrict__ flag2,
    int n, int E, int ch) {
    __shared__ int wsum[32];
    __shared__ int sp[NB_SCAN];
    __shared__ int s_base;

    const int b = (int)blockIdx.x;
    const int t = threadIdx.x;
    const int lane = t & 31;
    const int w = t >> 5;
    const int nb = (int)gridDim.x;

    // ---- phase 1: local chunk scan over PADDED counts ----
    int i = b * ch + t;
    int c = (t < ch && i < n) ? cnt[i] : 0;
    int pc = (c + 3) & ~3;
    int incl = pc;
#pragma unroll
    for (int o = 1; o < 32; o <<= 1) {
        int u = __shfl_up_sync(0xffffffffu, incl, o);
        if (lane >= o) incl += u;
    }
    if (lane == 31) wsum[w] = incl;
    __syncthreads();
    if (t < 32) {
        int v = wsum[t];
        int orig = v;
#pragma unroll
        for (int o = 1; o < 32; o <<= 1) {
            int u = __shfl_up_sync(0xffffffffu, v, o);
            if (t >= o) v += u;
        }
        int total = __shfl_sync(0xffffffffu, v, 31);
        wsum[t] = v - orig;
        if (t == 0) {
            partial[b] = total;
            __threadfence();
            atomicAdd(flag1, 1);
            while (atomicAdd(flag1, 0) < nb) {}
            __threadfence();
        }
    }
    __syncthreads();

    // ---- phase 2: top scan of nb partials ----
    if (t < nb) sp[t] = partial[t];
    __syncthreads();
    for (int o = 1; o < nb; o <<= 1) {
        int v = (t < nb && t >= o) ? sp[t - o] : 0;
        __syncthreads();
        if (t < nb) sp[t] += v;
        __syncthreads();
    }
    if (t == 0) s_base = (b == 0) ? 0 : sp[b - 1];
    __syncthreads();

    int run = s_base + wsum[w] + (incl - pc);
    if (t < ch && i < n) {
        off[i] = run;
        cur[i] = run;
        dinv[i] = rsqrtf((float)(c + 1));
        cnt[i] = 0;
        for (int p = run + c; p < run + pc; ++p) {
            esrc[p] = 0;
            ew[p] = 0.f;
        }
    }
    if (b == 0 && t == 0) off[n] = sp[nb - 1];

    // ---- grid barrier 2 ----
    __threadfence();
    __syncthreads();
    if (t == 0) {
        atomicAdd(flag2, 1);
        while (atomicAdd(flag2, 0) < nb) {}
        __threadfence();
    }
    __syncthreads();

    // ---- phase 3: CSR fill (grid-stride) ----
    for (int e = b * 1024 + t; e < E; e += nb * 1024) {
        int s = src[e];
        int d = dst[e];
        int pos = atomicAdd(&cur[d], 1);
        esrc[pos] = s;
        ew[pos] = dinv[s] * dinv[d];
    }
}

// ---------------------------------------------------------------------------
// Aggregation: fp16 gather, fp32 accumulate, fp16 out. Padded-4 CSR:
// per 4 edges one int4 + one float4 meta load, no tail loop.
// ---------------------------------------------------------------------------
__device__ __forceinline__ void fma_h4(float4& acc, float w, uint2 u) {
    __half2 a = *(__half2*)&u.x;
    __half2 b = *(__half2*)&u.y;
    float2 fa = __half22float2(a);
    float2 fb = __half22float2(b);
    acc.x = fmaf(w, fa.x, acc.x);
    acc.y = fmaf(w, fa.y, acc.y);
    acc.z = fmaf(w, fb.x, acc.z);
    acc.w = fmaf(w, fb.y, acc.w);
}

__global__ __launch_bounds__(256) void agg_kernel(const __half* __restrict__ h16,
                                                  const float* __restrict__ dinv,
                                                  const int* __restrict__ off,
                                                  const int* __restrict__ esrc,
                                                  const float* __restrict__ ew,
                                                  __half* __restrict__ out16, int n) {
    int node = (blockIdx.x * blockDim.x + threadIdx.x) >> 5;
    int lane = threadIdx.x & 31;
    if (node >= n) return;

    const uint2* __restrict__ h2 = (const uint2*)h16;
    float di = dinv[node];
    float wself = di * di;
    float4 acc = make_float4(0.f, 0.f, 0.f, 0.f);
    fma_h4(acc, wself, h2[(size_t)node * 32 + lane]);

    int e = off[node], e1 = off[node + 1];
    for (; e < e1; e += 4) {
        int4 si = __ldg((const int4*)(esrc + e));
        float4 wf = __ldg((const float4*)(ew + e));
        uint2 v0 = h2[(size_t)si.x * 32 + lane];
        uint2 v1 = h2[(size_t)si.y * 32 + lane];
        uint2 v2 = h2[(size_t)si.z * 32 + lane];
        uint2 v3 = h2[(size_t)si.w * 32 + lane];
        fma_h4(acc, wf.x, v0);
        fma_h4(acc, wf.y, v1);
        fma_h4(acc, wf.z, v2);
        fma_h4(acc, wf.w, v3);
    }
    __half2 o0 = __floats2half2_rn(acc.x, acc.y);
    __half2 o1 = __floats2half2_rn(acc.z, acc.w);
    uint2 u;
    u.x = *(uint32_t*)&o0;
    u.y = *(uint32_t*)&o1;
    ((uint2*)out16)[(size_t)node * 32 + lane] = u;
}

// ---------------------------------------------------------------------------
// fp16 HMMA GEMM, 128x128 tile, A staged in smem + ldmatrix fragment loads.
// W^T in smem stride 68 u32 (conflict-free); A in smem stride 136 halves
// (272 B: consecutive rows offset 4 banks => ldmatrix conflict-free).
// ---------------------------------------------------------------------------
#define BSTRIDE_U32 68
#define ASTRIDE_H 136
#define GEMM_SMEM (128 * BSTRIDE_U32 * 4 + 128 * ASTRIDE_H * 2)  // 69,632 B

__device__ __forceinline__ void mma_f16(float* c, const uint32_t* a, uint32_t b0, uint32_t b1) {
    asm volatile(
        "mma.sync.aligned.m16n8k16.row.col.f32.f16.f16.f32 "
        "{%0,%1,%2,%3}, {%4,%5,%6,%7}, {%8,%9}, {%0,%1,%2,%3};"
        : "+f"(c[0]), "+f"(c[1]), "+f"(c[2]), "+f"(c[3])
        : "r"(a[0]), "r"(a[1]), "r"(a[2]), "r"(a[3]), "r"(b0), "r"(b1));
}

template <int RELU, int F16OUT>
__global__ __launch_bounds__(256) void gemm_f16_kernel(
    const __half* __restrict__ A,
    const __half* __restrict__ Wt,
    const float* __restrict__ bias, float* __restrict__ C32,
    __half* __restrict__ C16, int n) {
    extern __shared__ uint32_t sm[];
    uint32_t* sB = sm;                                  // 128*68 u32
    __half* sA = (__half*)(sm + 128 * BSTRIDE_U32);     // 128 rows * 136 halves

    const int tid = threadIdx.x;
    const int warp = tid >> 5;
    const int lane = tid & 31;
    const int quad = lane >> 2;
    const int tq = lane & 3;
    const int row0 = blockIdx.x * 128;

    // stage W (coalesced)
    const uint32_t* W32 = (const uint32_t*)Wt;
#pragma unroll
    for (int i = tid; i < 128 * 64; i += 256) {
        int r = i >> 6, kp = i & 63;
        sB[r * BSTRIDE_U32 + kp] = W32[i];
    }
    // stage A tile (coalesced uint4: 2048 x 16B)
    const uint4 z4 = make_uint4(0, 0, 0, 0);
#pragma unroll
    for (int i = tid; i < 2048; i += 256) {
        int r = i >> 4, cq = i & 15;  // cq-th 16B chunk = halves 8cq..8cq+7
        int gr = row0 + r;
        uint4 v = (gr < n) ? ((const uint4*)(A + (size_t)gr * DD))[cq] : z4;
        *(uint4*)(sA + r * ASTRIDE_H + cq * 8) = v;
    }
    __syncthreads();

    const int row_lo = row0 + warp * 16 + quad;
    const int row_hi = row_lo + 8;
    const bool ok_lo = row_lo < n;
    const bool ok_hi = row_hi < n;

    // ldmatrix source address (per-lane): row = warp*16 + (lane&15), col = (lane>>4)*8
    const __half* a_base = sA + (warp * 16 + (lane & 15)) * ASTRIDE_H + ((lane >> 4) << 3);
    uint32_t a_addr = (uint32_t)__cvta_generic_to_shared(a_base);

    float acc[16][4];
#pragma unroll
    for (int t = 0; t < 16; ++t)
#pragma unroll
        for (int j = 0; j < 4; ++j) acc[t][j] = 0.f;

#pragma unroll
    for (int ks = 0; ks < 8; ++ks) {
        uint32_t a[4];
        asm volatile(
            "ldmatrix.sync.aligned.m8n8.x4.shared.b16 {%0,%1,%2,%3}, [%4];"
            : "=r"(a[0]), "=r"(a[1]), "=r"(a[2]), "=r"(a[3])
            : "r"(a_addr + ks * 32));  // +16 halves per kstep = 32 B
        const int kbase = ks * 8 + tq;
#pragma unroll
        for (int nt = 0; nt < 16; ++nt) {
            int brow = nt * 8 + quad;
            uint32_t b0 = sB[brow * BSTRIDE_U32 + kbase];
            uint32_t b1 = sB[brow * BSTRIDE_U32 + kbase + 4];
            mma_f16(acc[nt], a, b0, b1);
        }
    }

#pragma unroll
    for (int nt = 0; nt < 16; ++nt) {
        int col = nt * 8 + 2 * tq;
        float2 bv = *(const float2*)(bias + col);
        float c0 = acc[nt][0] + bv.x, c1 = acc[nt][1] + bv.y;
        float c2 = acc[nt][2] + bv.x, c3 = acc[nt][3] + bv.y;
        if (RELU) {
            c0 = fmaxf(c0, 0.f); c1 = fmaxf(c1, 0.f);
            c2 = fmaxf(c2, 0.f); c3 = fmaxf(c3, 0.f);
        }
        if (F16OUT) {
            if (ok_lo) *(__half2*)(C16 + (size_t)row_lo * DD + col) = __floats2half2_rn(c0, c1);
            if (ok_hi) *(__half2*)(C16 + (size_t)row_hi * DD + col) = __floats2half2_rn(c2, c3);
        } else {
            if (ok_lo) *(float2*)(C32 + (size_t)row_lo * DD + col) = make_float2(c0, c1);
            if (ok_hi) *(float2*)(C32 + (size_t)row_hi * DD + col) = make_float2(c2, c3);
        }
    }
}

// ---------------------------------------------------------------------------
// Launch: 8 kernels total (prep, scanfill, 3x[agg, gemm])
// ---------------------------------------------------------------------------
extern "C" void kernel_launch(void* const* d_in, const int* in_sizes, int n_in,
                              void* d_out, int out_size) {
    const float* x  = (const float*)d_in[0];
    const int*   ei = (const int*)d_in[1];
    const float* W1 = (const float*)d_in[2];
    const float* b1 = (const float*)d_in[3];
    const float* W2 = (const float*)d_in[4];
    const float* b2 = (const float*)d_in[5];
    const float* W3 = (const float*)d_in[6];
    const float* b3 = (const float*)d_in[7];

    int n = in_sizes[0] / DD;
    int E = in_sizes[1] / 2;
    const int* src = ei;
    const int* dst = ei + E;

    float *dinv, *ew;
    __half *y16, *x16, *act16, *w16;
    int *cnt, *off, *cur, *esrc, *partial, *flag1, *flag2;
    cudaGetSymbolAddress((void**)&y16, g_y16);
    cudaGetSymbolAddress((void**)&x16, g_x16);
    cudaGetSymbolAddress((void**)&act16, g_act16);
    cudaGetSymbolAddress((void**)&w16, g_w16);
    cudaGetSymbolAddress((void**)&dinv, g_dinv);
    cudaGetSymbolAddress((void**)&cnt, g_cnt);
    cudaGetSymbolAddress((void**)&off, g_off);
    cudaGetSymbolAddress((void**)&cur, g_cur);
    cudaGetSymbolAddress((void**)&esrc, g_esrc);
    cudaGetSymbolAddress((void**)&ew, g_ew);
    cudaGetSymbolAddress((void**)&partial, g_partial);
    cudaGetSymbolAddress((void**)&flag1, g_flag1);
    cudaGetSymbolAddress((void**)&flag2, g_flag2);

    float* outp = (float*)d_out;

    cudaFuncSetAttribute(gemm_f16_kernel<1, 1>, cudaFuncAttributeMaxDynamicSharedMemorySize,
                         GEMM_SMEM);
    cudaFuncSetAttribute(gemm_f16_kernel<0, 0>, cudaFuncAttributeMaxDynamicSharedMemorySize,
                         GEMM_SMEM);

    int tot4 = n * (DD / 4);
    int ncb = (E + 255) / 256;
    int wsb = (3 * DD * DD + 255) / 256;
    int cvb = (tot4 + 255) / 256;
    int ch = (n + NB_SCAN - 1) / NB_SCAN;

    // --- preprocess: 2 launches ---
    prep_kernel<<<ncb + wsb + cvb, 256>>>(dst, cnt, E, ncb, W1, W2, W3, w16, wsb, x, x16,
                                          tot4, flag1, flag2);
    scanfill_kernel<<<NB_SCAN, 1024>>>(cnt, off, cur, dinv, src, dst, esrc, ew, partial,
                                       flag1, flag2, n, E, ch);

    int gemm_grid = (n + 127) / 128;
    int agg_grid = (n + 7) / 8;

    // Layer 1
    agg_kernel<<<agg_grid, 256>>>(x16, dinv, off, esrc, ew, y16, n);
    gemm_f16_kernel<1, 1><<<gemm_grid, 256, GEMM_SMEM>>>(y16, w16, b1, nullptr, act16, n);
    // Layer 2
    agg_kernel<<<agg_grid, 256>>>(act16, dinv, off, esrc, ew, y16, n);
    gemm_f16_kernel<1, 1><<<gemm_grid, 256, GEMM_SMEM>>>(y16, w16 + DD * DD, b2, nullptr,
                                                         act16, n);
    // Layer 3 (no relu) -> fp32 d_out
    agg_kernel<<<agg_grid, 256>>>(act16, dinv, off, esrc, ew, y16, n);
    gemm_f16_kernel<0, 0><<<gemm_grid, 256, GEMM_SMEM>>>(y16, w16 + 2 * DD * DD, b3, outp,
                                                         nullptr, n);
}